// round 11
// baseline (speedup 1.0000x reference)
#include <cuda_runtime.h>
#include <cuda_bf16.h>
#include <mma.h>
#include <math.h>

using namespace nvcuda;

// Problem constants
#define BS   8
#define NQ   4096
#define E    256
#define NH   8
#define NP   4
#define HD   32
#define HH   64
#define WW   64
#define M_TOT (BS*NQ)      // 32768
#define N1   352

// GEMM tiling
#define BM   128
#define BN   128
#define BK   32
#define LDAH 40                    // bf16 leading dim (80B rows)
#define LDC  136                   // float C staging leading dim
#define NKT  (E/BK)                // 8
#define STAGE ((BM+BN)*LDAH)       // 10240 bf16 per stage
#define DYN_SMEM 69632             // max(3*STAGE*2 = 61440, BM*LDC*4 = 69632)

// Scratch
__device__ __nv_bfloat16 g_qb  [M_TOT*E];             // query bf16
__device__ __nv_bfloat16 g_val [BS*NH*NQ*HD + 4096];  // [b,h,pos,d] + guard pad
__device__ float         g_off [M_TOT*64];
__device__ float         g_attn[M_TOT*32];
__device__ __nv_bfloat16 g_samp[M_TOT*E];
__device__ __nv_bfloat16 g_w1  [N1*E];
__device__ __nv_bfloat16 g_w2  [E*E];
__device__ float         g_b1  [N1];
__device__ float4        g_sw  [M_TOT*NH*NP];         // premult corner weights
__device__ int           g_sidx[M_TOT*NH*NP];         // clamped base index

// ---------------------------------------------------------------------------
__device__ __forceinline__ void cp_async16(void* sdst, const void* gsrc) {
    unsigned s = (unsigned)__cvta_generic_to_shared(sdst);
    asm volatile("cp.async.cg.shared.global [%0], [%1], 16;\n" :: "r"(s), "l"(gsrc));
}

// ---------------------------------------------------------------------------
// Prep (fused): blocks [0,4096) convert query fp32->bf16; blocks [4096,4448)
// convert/concat weights and biases.
// ---------------------------------------------------------------------------
__global__ __launch_bounds__(256) void prep_all(
        const float* __restrict__ qsrc,
        const float* __restrict__ vw, const float* __restrict__ vb,
        const float* __restrict__ ow, const float* __restrict__ ob,
        const float* __restrict__ aw, const float* __restrict__ ab,
        const float* __restrict__ outw) {
    if (blockIdx.x < 4096) {
        int i = (blockIdx.x * 256 + threadIdx.x) * 8;
        float4 u = *(const float4*)&qsrc[i];
        float4 v = *(const float4*)&qsrc[i + 4];
        __nv_bfloat16 t[8] = {
            __float2bfloat16(u.x), __float2bfloat16(u.y),
            __float2bfloat16(u.z), __float2bfloat16(u.w),
            __float2bfloat16(v.x), __float2bfloat16(v.y),
            __float2bfloat16(v.z), __float2bfloat16(v.w)};
        *(uint4*)&g_qb[i] = *(uint4*)t;
    } else {
        int i = (blockIdx.x - 4096) * 256 + threadIdx.x;
        if (i < 256*256)      g_w1[i] = __float2bfloat16(vw[i]);
        else if (i < 320*256) g_w1[i] = __float2bfloat16(ow[i - 256*256]);
        else if (i < 352*256) g_w1[i] = __float2bfloat16(aw[i - 320*256]);
        if (i < 256*256)      g_w2[i] = __float2bfloat16(outw[i]);
        if (i < 256)          g_b1[i] = vb[i];
        else if (i < 320)     g_b1[i] = ob[i - 256];
        else if (i < 352)     g_b1[i] = ab[i - 320];
    }
}

// ---------------------------------------------------------------------------
// bf16 3-stage cp.async pipelined mainloop: C = A @ B^T staged to smem (fp32).
// ---------------------------------------------------------------------------
__device__ __forceinline__ void bf16_mainloop(
    const __nv_bfloat16* __restrict__ A, const __nv_bfloat16* __restrict__ B,
    int b_rows, int m0, int n0, unsigned char* smem_raw)
{
    __nv_bfloat16* buf = (__nv_bfloat16*)smem_raw;
    const int tid  = threadIdx.x;
    const int warp = tid >> 5;
    const int wr   = warp >> 2;    // 0..1 -> 64-row block
    const int wc   = warp & 3;     // 0..3 -> 32-col block

    wmma::fragment<wmma::accumulator, 16, 16, 16, float> c[4][2];
    #pragma unroll
    for (int i = 0; i < 4; i++)
        #pragma unroll
        for (int j = 0; j < 2; j++) wmma::fill_fragment(c[i][j], 0.0f);

    auto issue = [&](int s, int k0) {
        __nv_bfloat16* St = buf + s * STAGE;
        #pragma unroll
        for (int it = 0; it < 4; it++) {
            int idx = tid + it * 256;
            int row = idx >> 2, cg = idx & 3;
            const __nv_bfloat16* src;
            if (row < BM) {
                src = A + (size_t)(m0 + row) * E + k0 + cg * 8;
            } else {
                int gn = n0 + row - BM;
                if (gn >= b_rows) gn = b_rows - 1;
                src = B + (size_t)gn * E + k0 + cg * 8;
            }
            cp_async16(St + row * LDAH + cg * 8, src);
        }
        asm volatile("cp.async.commit_group;\n" ::);
    };

    auto compute = [&](int s) {
        __nv_bfloat16* As = buf + s * STAGE;
        __nv_bfloat16* Bs = As + BM * LDAH;
        #pragma unroll
        for (int kk = 0; kk < BK; kk += 16) {
            wmma::fragment<wmma::matrix_a, 16, 16, 16, __nv_bfloat16, wmma::row_major> a[4];
            wmma::fragment<wmma::matrix_b, 16, 16, 16, __nv_bfloat16, wmma::col_major> b[2];
            #pragma unroll
            for (int i = 0; i < 4; i++)
                wmma::load_matrix_sync(a[i], &As[(wr * 64 + i * 16) * LDAH + kk], LDAH);
            #pragma unroll
            for (int j = 0; j < 2; j++)
                wmma::load_matrix_sync(b[j], &Bs[(wc * 32 + j * 16) * LDAH + kk], LDAH);
            #pragma unroll
            for (int i = 0; i < 4; i++)
                #pragma unroll
                for (int j = 0; j < 2; j++)
                    wmma::mma_sync(c[i][j], a[i], b[j], c[i][j]);
        }
    };

    issue(0, 0);
    issue(1, BK);
    #pragma unroll
    for (int kt = 0; kt < NKT; kt++) {
        if (kt < NKT - 1) { asm volatile("cp.async.wait_group 1;\n" ::); }
        else              { asm volatile("cp.async.wait_group 0;\n" ::); }
        __syncthreads();
        compute(kt % 3);
        if (kt + 2 < NKT) issue((kt + 2) % 3, (kt + 2) * BK);
    }
    __syncthreads();

    float* Cs = (float*)smem_raw;
    #pragma unroll
    for (int i = 0; i < 4; i++)
        #pragma unroll
        for (int j = 0; j < 2; j++)
            wmma::store_matrix_sync(&Cs[(wr * 64 + i * 16) * LDC + wc * 32 + j * 16],
                                    c[i][j], LDC, wmma::mem_row_major);
    __syncthreads();
}

// ---------------------------------------------------------------------------
// GEMM1: g_qb @ g_w1^T (+bias) -> scatter {g_val bf16, g_off, g_attn}
// ---------------------------------------------------------------------------
__global__ __launch_bounds__(256) void gemm1_tc() {
    extern __shared__ unsigned char smem_raw[];
    const int m0 = blockIdx.x * BM;
    const int n0 = blockIdx.y * BN;
    const int tid = threadIdx.x;

    bf16_mainloop(g_qb, g_w1, N1, m0, n0, smem_raw);
    float* Cs = (float*)smem_raw;

    #pragma unroll
    for (int it = 0; it < 16; it++) {
        int idx = tid + it * 256;
        int mm = idx >> 5, n4 = idx & 31;
        int c = n0 + n4 * 4;
        if (c >= N1) continue;
        int m = m0 + mm;
        int b = m >> 12, q = m & 4095;
        float4 v = *(float4*)&Cs[mm * LDC + n4 * 4];
        v.x += g_b1[c];     v.y += g_b1[c + 1];
        v.z += g_b1[c + 2]; v.w += g_b1[c + 3];
        if (c < 256) {
            int h = c >> 5, d = c & 31;
            __nv_bfloat16 t[4] = {__float2bfloat16(v.x), __float2bfloat16(v.y),
                                  __float2bfloat16(v.z), __float2bfloat16(v.w)};
            *(uint2*)&g_val[((((size_t)b << 3) + h) * NQ + q) * HD + d] = *(uint2*)t;
        } else if (c < 320) {
            *(float4*)&g_off[(size_t)m * 64 + (c - 256)] = v;
        } else {
            *(float4*)&g_attn[(size_t)m * 32 + (c - 320)] = v;
        }
    }
}

// ---------------------------------------------------------------------------
// GEMM2: g_samp @ g_w2^T + out_b + 2*query -> out
// ---------------------------------------------------------------------------
__global__ __launch_bounds__(256) void gemm2_tc(const float* __restrict__ bias,
                                                const float* __restrict__ query,
                                                float* __restrict__ out) {
    extern __shared__ unsigned char smem_raw[];
    const int m0 = blockIdx.x * BM;
    const int n0 = blockIdx.y * BN;
    const int tid = threadIdx.x;

    bf16_mainloop(g_samp, g_w2, E, m0, n0, smem_raw);
    float* Cs = (float*)smem_raw;

    #pragma unroll
    for (int it = 0; it < 16; it++) {
        int idx = tid + it * 256;
        int mm = idx >> 5, n4 = idx & 31;
        int c = n0 + n4 * 4;
        size_t go = (size_t)(m0 + mm) * E + c;
        float4 v = *(float4*)&Cs[mm * LDC + n4 * 4];
        float4 bi = *(const float4*)&bias[c];
        float4 qv = *(const float4*)&query[go];
        v.x += bi.x + 2.0f * qv.x;
        v.y += bi.y + 2.0f * qv.y;
        v.z += bi.z + 2.0f * qv.z;
        v.w += bi.w + 2.0f * qv.w;
        *(float4*)&out[go] = v;
    }
}

// ---------------------------------------------------------------------------
// Sample setup: one thread per (m,h,p). Softmax-premultiplied, validity-masked
// corner weights + clamped base index (low-side clamp folds weight into base).
// ---------------------------------------------------------------------------
__global__ __launch_bounds__(256) void sample_setup() {
    const int t  = blockIdx.x * 256 + threadIdx.x;
    const int p  = t & 3;
    const int mh = t >> 2;          // m*8 + h
    const int m  = mh >> 3;
    const int q  = m & 4095;

    const float4 at = *(const float4*)&g_attn[(size_t)mh * 4];
    float mx = fmaxf(fmaxf(at.x, at.y), fmaxf(at.z, at.w));
    float e0 = __expf(at.x - mx), e1 = __expf(at.y - mx),
          e2 = __expf(at.z - mx), e3 = __expf(at.w - mx);
    float inv = 1.f / (e0 + e1 + e2 + e3);
    float awp = (p == 0 ? e0 : p == 1 ? e1 : p == 2 ? e2 : e3) * inv;

    const float2 off = *(const float2*)&g_off[(size_t)mh * 8 + p * 2];
    const float px = (float)(q & 63) * (64.0f / 63.0f) + off.x - 0.5f;
    const float py = (float)(q >> 6) * (64.0f / 63.0f) + off.y - 0.5f;
    const float fx = floorf(px), fy = floorf(py);
    const float wx = px - fx, wy = py - fy;
    const int ix = (int)fx, iy = (int)fy;

    float wxl = (ix >= 0  && ix < 64) ? (1.f - wx) : 0.f;
    float wxr = (ix >= -1 && ix < 63) ? wx         : 0.f;
    if (ix < 0) { wxl = wxr; wxr = 0.f; }
    float wyt = (iy >= 0  && iy < 64) ? (1.f - wy) : 0.f;
    float wyb = (iy >= -1 && iy < 63) ? wy         : 0.f;
    if (iy < 0) { wyt = wyb; wyb = 0.f; }
    wyt *= awp;
    wyb *= awp;

    const int ix0 = min(max(ix, 0), 63);
    const int iy0 = min(max(iy, 0), 63);

    g_sw[t]   = make_float4(wxl * wyt, wxr * wyt, wxl * wyb, wxr * wyb);
    g_sidx[t] = (iy0 << 11) + (ix0 << 5);
}

// ---------------------------------------------------------------------------
// Gather v2: warp = (m, head-pair). Lane: b4=head, b3=point-pair, b2-0=lane8.
// Each 8-lane group loads a 128B row span covering BOTH x-corners of one
// point's tap (lane8 bit2 = corner). 4 unrolled iterations cover
// (point-in-pair, y-row). Output sums over points anyway, so each lane just
// accumulates; reduce over lane bits {3,2} via shfl.
// ---------------------------------------------------------------------------
__global__ __launch_bounds__(256) void sample_gather() {
    const int wid  = blockIdx.x * 8 + (threadIdx.x >> 5);  // 0 .. M_TOT*4-1
    const int lane = threadIdx.x & 31;
    const int m    = wid >> 2;
    const int h    = ((wid & 3) << 1) + (lane >> 4);       // 0..7
    const int sub  = (lane >> 3) & 1;                      // point-pair
    const int l8   = lane & 7;
    const int corner = (l8 >> 2) & 1;
    const int mh   = (m << 3) + h;
    const int slab = ((m >> 12) << 3) + h;                 // b*8+h

    const int t0 = (mh << 2) + (sub << 1);                 // even
    const float4 w0 = __ldg(&g_sw[t0]);
    const float4 w1 = __ldg(&g_sw[t0 + 1]);
    const int2  bb  = __ldg((const int2*)&g_sidx[t0]);

    const __nv_bfloat16* __restrict__ vp =
        g_val + (size_t)slab * (NQ * HD) + (l8 << 3);

    float acc[8];
    #pragma unroll
    for (int j = 0; j < 8; j++) acc[j] = 0.f;

    #pragma unroll
    for (int i = 0; i < 4; i++) {
        const int   base = (i < 2) ? bb.x : bb.y;
        const float4 w   = (i < 2) ? w0   : w1;
        const int   row  = i & 1;
        const float cw = row ? (corner ? w.w : w.z)
                             : (corner ? w.y : w.x);
        uint4 r = *(const uint4*)(vp + base + (row << 11));
        const __nv_bfloat162* h2 = (const __nv_bfloat162*)&r;
        #pragma unroll
        for (int j = 0; j < 4; j++) {
            float2 f = __bfloat1622float2(h2[j]);
            acc[2*j]   = fmaf(cw, f.x, acc[2*j]);
            acc[2*j+1] = fmaf(cw, f.y, acc[2*j+1]);
        }
    }

    // reduce over point-pair (bit 3) and x-corner (bit 2)
    #pragma unroll
    for (int msk = 8; msk >= 4; msk >>= 1)
        #pragma unroll
        for (int j = 0; j < 8; j++)
            acc[j] += __shfl_xor_sync(0xFFFFFFFF, acc[j], msk);

    if ((lane & 12) == 0) {
        __nv_bfloat16 tt[8];
        #pragma unroll
        for (int j = 0; j < 8; j++) tt[j] = __float2bfloat16(acc[j]);
        *(uint4*)&g_samp[(size_t)m * E + h * HD + ((lane & 3) << 3)] = *(uint4*)tt;
    }
}

// ---------------------------------------------------------------------------
extern "C" void kernel_launch(void* const* d_in, const int* in_sizes, int n_in,
                              void* d_out, int out_size) {
    const float* query   = (const float*)d_in[0];
    const float* value_w = (const float*)d_in[1];
    const float* value_b = (const float*)d_in[2];
    const float* off_w   = (const float*)d_in[3];
    const float* off_b   = (const float*)d_in[4];
    const float* attn_w  = (const float*)d_in[5];
    const float* attn_b  = (const float*)d_in[6];
    const float* out_w   = (const float*)d_in[7];
    const float* out_b   = (const float*)d_in[8];
    float* out = (float*)d_out;

    static bool attr_done = false;
    if (!attr_done) {
        cudaFuncSetAttribute(gemm1_tc, cudaFuncAttributeMaxDynamicSharedMemorySize, DYN_SMEM);
        cudaFuncSetAttribute(gemm2_tc, cudaFuncAttributeMaxDynamicSharedMemorySize, DYN_SMEM);
        attr_done = true;
    }

    prep_all<<<4096 + 352, 256>>>(query, value_w, value_b, off_w, off_b,
                                  attn_w, attn_b, out_w);

    dim3 g1(M_TOT / BM, (N1 + BN - 1) / BN);   // 256 x 3
    gemm1_tc<<<g1, 256, DYN_SMEM>>>();

    sample_setup<<<(M_TOT * NH * NP) / 256, 256>>>();
    sample_gather<<<(M_TOT * 4) / 8, 256>>>();

    dim3 g2(M_TOT / BM, E / BN);               // 256 x 2
    gemm2_tc<<<g2, 256, DYN_SMEM>>>(out_b, query, out);
}